// round 16
// baseline (speedup 1.0000x reference)
#include <cuda_runtime.h>

// CRF forward log-partition. B=512, T=512, L=64.
// TIME-SPLIT + PAIR-LOCAL SYNC: block = 128 thr = 1 batch (grid 512 -> 2048 warps).
// Warps {0,1} forward, {2,3} backward. Warp wp of a pair owns tags wp*32..wp*32+31,
// lane owns ONE tag, full 64-prev dot (32 FFMA2 pair-packed, 4 chains depth 8).
// v exchange: STS.32 + named barrier `bar.sync 1+dir, 64` (couples only the 2 warps
// of the direction pair -- no block-wide jitter; this is what R10 got wrong).
// Renorm every 4 rounds: per-warp shfl-max at s==2 -> red_sh[dir][wp]; both warps
// combine + apply at next s==0 (acc2 committed at APPLY; final pending discarded).
// Emissions: 1 float/lane/round, prefetch distance 2, ex2 off the chain.
// Combine: Z = sum_n v_fwd[n]*w_bwd[n]; log2 scales add.

#define LOG2E 1.4426950408889634f
#define LN2   0.6931471805599453f

constexpr int L    = 64;
constexpr int TT   = 512;
constexpr int HALF = 256;

static __device__ __forceinline__ float ex2f(float x) {
    float r; asm("ex2.approx.ftz.f32 %0, %1;" : "=f"(r) : "f"(x)); return r;
}
static __device__ __forceinline__ float lg2f(float x) {
    float r; asm("lg2.approx.ftz.f32 %0, %1;" : "=f"(r) : "f"(x)); return r;
}
static __device__ __forceinline__ unsigned long long pk2(float lo, float hi) {
    unsigned long long r;
    asm("mov.b64 %0, {%1, %2};" : "=l"(r) : "f"(lo), "f"(hi)); return r;
}
static __device__ __forceinline__ void upk2(unsigned long long v, float& lo, float& hi) {
    asm("mov.b64 {%0, %1}, %2;" : "=f"(lo), "=f"(hi) : "l"(v));
}
static __device__ __forceinline__ unsigned long long ffma2(
    unsigned long long a, unsigned long long b, unsigned long long c) {
    unsigned long long d;
    asm("fma.rn.f32x2 %0, %1, %2, %3;" : "=l"(d) : "l"(a), "l"(b), "l"(c)); return d;
}
static __device__ __forceinline__ unsigned long long fadd2(
    unsigned long long a, unsigned long long b) {
    unsigned long long d;
    asm("add.rn.f32x2 %0, %1, %2;" : "=l"(d) : "l"(a), "l"(b)); return d;
}
static __device__ __forceinline__ void bar64(int id) {
    asm volatile("bar.sync %0, 64;" :: "r"(id) : "memory");
}

__global__ __launch_bounds__(128, 4) void crf_fwd(
    const float* __restrict__ emis,   // [B, T, L]
    const float* __restrict__ trans,  // [L, L]  trans[next*L + prev]
    float* __restrict__ out)          // [B]
{
    const int b    = blockIdx.x;
    const int tid  = threadIdx.x;
    const int w    = tid >> 5;       // warp 0..3
    const int lane = tid & 31;
    const int dir  = w >> 1;         // 0 = forward (warps 0,1), 1 = backward (2,3)
    const int wp   = w & 1;          // warp within pair
    const int n    = wp * 32 + lane; // owned tag
    const int bid  = 1 + dir;        // named barrier id for this pair
    const unsigned FULL = 0xffffffffu;

    __shared__ __align__(16) float v_sh[2][2][L];   // [dir][buf][tag]
    __shared__ __align__(16) float red_sh[2][2];    // [dir][wp]
    __shared__ __align__(16) float fin[2][L];
    __shared__ int acc_sh[2];

    // ---- E vector for this tag, consecutive-pair packed: E[j]=(e[2j], e[2j+1]) ----
    unsigned long long E[32];
    if (dir == 0) {
        const float4* tr = reinterpret_cast<const float4*>(trans + n * L);
        #pragma unroll
        for (int j = 0; j < 16; j++) {
            float4 a = tr[j];
            E[2 * j]     = pk2(__expf(a.x), __expf(a.y));
            E[2 * j + 1] = pk2(__expf(a.z), __expf(a.w));
        }
    } else {
        #pragma unroll
        for (int j = 0; j < 32; j++) {
            E[j] = pk2(__expf(trans[(2 * j)     * L + n]),
                       __expf(trans[(2 * j + 1) * L + n]));
        }
    }

    // ---- init state ----
    if (dir == 0) {
        v_sh[0][0][n] = (n == L - 2) ? 1.0f : 0.0f;    // delta(START=62)
    } else {
        float es = __expf(trans[(L - 1) * L + n]);      // exp(trans[STOP][n])
        float fe = ex2f(__ldg(emis + (size_t)b * (TT * L) + 511 * L + n) * LOG2E);
        v_sh[1][0][n] = es * fe;
    }
    if (lane == 0) red_sh[dir][wp] = 1.0f;

    // ---- emission stream: fwd t=0.. ascending; bwd t=510.. descending ----
    const int dstep = dir ? -L : L;
    const float* eptr = emis + (size_t)b * (TT * L) + (dir ? 510 * L : 0) + n;
    float eA = ex2f(__ldg(eptr) * LOG2E);
    float eB = ex2f(__ldg(eptr + dstep) * LOG2E);
    const float* pf = eptr + 2 * dstep;

    int   acc2 = 0;
    float v    = 0.0f;
    int   buf  = 0;
    __syncthreads();

    #pragma unroll 1
    for (int it = 0; it < HALF / 4; ++it) {
        #pragma unroll
        for (int s = 0; s < 4; ++s) {
            const int j = it * 4 + s;

            float f = eA;
            if (s == 0) {
                // combine pair maxes (written at s==2, ordered by s==2/s==3 barriers)
                float2 rv = *reinterpret_cast<const float2*>(red_sh[dir]);
                float m = fmaxf(rv.x, rv.y);
                int ei = (int)((__float_as_uint(m) >> 23) & 0xff);
                float scale = __uint_as_float((unsigned)(253 - ei) << 23); // 2^(126-ei)
                acc2 += ei - 126;    // committed at APPLY time
                f *= scale;
            }

            // ---- full 64-prev dot: 16 broadcast LDS.128, 32 FFMA2 (4 chains x8) ----
            const ulonglong2* vv =
                reinterpret_cast<const ulonglong2*>(&v_sh[dir][buf][0]);
            unsigned long long c0, c1, c2, c3;
            {
                ulonglong2 qa = vv[0], qb = vv[1];
                c0 = ffma2(qa.x, E[0], 0ull);
                c1 = ffma2(qa.y, E[1], 0ull);
                c2 = ffma2(qb.x, E[2], 0ull);
                c3 = ffma2(qb.y, E[3], 0ull);
            }
            #pragma unroll
            for (int k = 2; k < 16; k += 2) {
                ulonglong2 qa = vv[k], qb = vv[k + 1];
                c0 = ffma2(qa.x, E[2 * k],     c0);
                c1 = ffma2(qa.y, E[2 * k + 1], c1);
                c2 = ffma2(qb.x, E[2 * k + 2], c2);
                c3 = ffma2(qb.y, E[2 * k + 3], c3);
            }
            float s0;
            { float lo, hi; upk2(fadd2(fadd2(c0, c1), fadd2(c2, c3)), lo, hi); s0 = lo + hi; }

            v = s0 * f;
            v_sh[dir][buf ^ 1][n] = v;

            if (s == 2) {
                // per-warp max over this warp's 32 tags; shared with pair partner
                float wm = v;
                #pragma unroll
                for (int o = 16; o >= 1; o >>= 1)
                    wm = fmaxf(wm, __shfl_xor_sync(FULL, wm, o));
                if (lane == 0) red_sh[dir][wp] = wm;
            }

            // prefetch emission for round j+2 (bwd: mask rounds > 254 -> f = 1)
            {
                float r = __ldg(pf);
                pf += dstep;
                if (dir && (j + 2 > 254)) r = 0.0f;
                eA = eB;
                eB = ex2f(r * LOG2E);
            }

            bar64(bid);           // sync only the 2 warps of this direction
            buf ^= 1;
        }
    }

    // ---- combine: Z = sum_n v[n] * w[n]; scales add in log2 ----
    fin[dir][n] = v;
    if (tid == 0 || tid == 64) acc_sh[dir] = acc2;   // both warps of pair agree
    __syncthreads();
    if (tid < 32) {
        float p = fin[0][tid] * fin[1][tid] + fin[0][tid + 32] * fin[1][tid + 32];
        #pragma unroll
        for (int o = 16; o >= 1; o >>= 1) p += __shfl_xor_sync(FULL, p, o);
        if (tid == 0)
            out[b] = (lg2f(p) + (float)(acc_sh[0] + acc_sh[1])) * LN2;
    }
}

extern "C" void kernel_launch(void* const* d_in, const int* in_sizes, int n_in,
                              void* d_out, int out_size) {
    const float* emis  = (const float*)d_in[0];   // [B, T, L] float32
    const float* trans = (const float*)d_in[1];   // [L, L] float32
    float* out = (float*)d_out;                   // [B] float32
    int B = in_sizes[0] / (TT * L);
    crf_fwd<<<B, 128>>>(emis, trans, out);
}